// round 10
// baseline (speedup 1.0000x reference)
#include <cuda_runtime.h>
#include <math.h>

#define N_NODES 50000
#define N_EDGES 800000
#define D 64
#define GRID 148           // 1 CTA/SM, <= SM count (148 B300 / 152 GB300) => co-resident
#define THREADS 512
#define RANGE 338          // ceil(N_NODES / GRID); 148*338 = 50024
#define AH_STRIDE 136      // interleaved a/h rows: 2*64 + 8 pad
#define N_TILES 391        // ceil(N_NODES / 128)

typedef unsigned long long ull;

// ------------------------- device scratch (no allocs allowed) ---------------
// Referenced ONLY from device code (host-side use of a __device__ symbol
// passes the host shadow address, which ATS dereferences silently - R1/2 bug).
__device__ float g_wh[N_NODES * D];
__device__ float g_agg[N_NODES * D];
__device__ int   g_rowptr[N_NODES + 1];
__device__ int   g_cnt[N_NODES];
__device__ int   g_cursor[N_NODES];
__device__ int   g_srcsorted[N_EDGES];
__device__ int   g_chunksum[GRID];
__device__ int   g_chunkoff[GRID];
__device__ float g_wihT[64 * 192];
__device__ float g_whhT[64 * 192];
__device__ float g_wT[64 * 64];
__device__ float g_brz[128];
__device__ float g_bni[64];
__device__ float g_bnh[64];
// manual grid barrier state (zero-initialized at module load; count returns to
// 0 after every barrier, gen monotonically increases across replays - fine)
__device__ int          g_bar_count;
__device__ volatile int g_bar_gen;

// ------------------------- helpers ------------------------------------------
__device__ __forceinline__ ull ffma2(ull a, ull b, ull c) {
    ull d;
    asm("fma.rn.f32x2 %0, %1, %2, %3;" : "=l"(d) : "l"(a), "l"(b), "l"(c));
    return d;
}
__device__ __forceinline__ ull pack2f(float x, float y) {
    ull r;
    asm("mov.b64 %0, {%1, %2};" : "=l"(r) : "f"(x), "f"(y));
    return r;
}
__device__ __forceinline__ float2 unpack2(ull v) {
    float2 f;
    asm("mov.b64 {%0, %1}, %2;" : "=f"(f.x), "=f"(f.y) : "l"(v));
    return f;
}
__device__ __forceinline__ float sigmoid_fast(float x) {
    return __fdividef(1.0f, 1.0f + __expf(-x));
}
__device__ __forceinline__ float tanh_fast(float x) {
    // 1 - 2/(e^{2x}+1); exp overflow -> inf -> 1, underflow -> 0 -> -1 (correct)
    return 1.0f - __fdividef(2.0f, __expf(2.0f * x) + 1.0f);
}

// sense-reversing generation grid barrier (all CTAs co-resident by construction)
__device__ __forceinline__ void grid_sync() {
    __syncthreads();
    if (threadIdx.x == 0) {
        __threadfence();                         // release my CTA's writes
        int gen = g_bar_gen;
        if (atomicAdd(&g_bar_count, 1) == GRID - 1) {
            g_bar_count = 0;
            __threadfence();                     // count reset before gen flip
            g_bar_gen = gen + 1;
        } else {
            while (g_bar_gen == gen) { __nanosleep(32); }
        }
        __threadfence();                         // acquire others' writes
    }
    __syncthreads();
}

// block-wide inclusive scan over 512 threads (16 warps)
__device__ __forceinline__ int block_incl_scan(int v) {
    __shared__ int ws[16];
    int lane = threadIdx.x & 31, w = threadIdx.x >> 5;
    int x = v;
#pragma unroll
    for (int off = 1; off < 32; off <<= 1) {
        int y = __shfl_up_sync(0xffffffffu, x, off);
        if (lane >= off) x += y;
    }
    if (lane == 31) ws[w] = x;
    __syncthreads();
    if (w == 0 && lane < 16) {
        int s = ws[lane];
        int xs = s;
#pragma unroll
        for (int off = 1; off < 16; off <<= 1) {
            int y = __shfl_up_sync(0xffffu, xs, off);
            if (lane >= off) xs += y;
        }
        ws[lane] = xs - s;   // exclusive warp offsets
    }
    __syncthreads();
    int res = x + ws[w];
    __syncthreads();         // protect ws for the next call
    return res;
}

// ------------------------- prep: transposes + biases + zero counts ----------
__global__ void prep_kernel(const float* __restrict__ W,
                            const float* __restrict__ Wih,
                            const float* __restrict__ Whh,
                            const float* __restrict__ bih,
                            const float* __restrict__ bhh) {
    int i = blockIdx.x * blockDim.x + threadIdx.x;
    if (i < N_NODES) g_cnt[i] = 0;
    if (i < 12288) {
        int k = i / 192, j = i % 192;
        g_wihT[i] = Wih[j * 64 + k];
    } else if (i < 24576) {
        int e = i - 12288; int k = e / 192, j = e % 192;
        g_whhT[e] = Whh[j * 64 + k];
    } else if (i < 28672) {
        int e = i - 24576; int k = e / 64, j = e % 64;
        g_wT[e] = W[j * 64 + k];
    } else if (i < 28800) {
        int d = i - 28672;
        g_brz[d] = bih[d] + bhh[d];
    } else if (i < 28864) {
        int d = i - 28800;
        g_bni[d] = bih[128 + d];
    } else if (i < 28928) {
        int d = i - 28864;
        g_bnh[d] = bhh[128 + d];
    }
}

// ------------------------- the megakernel ------------------------------------
__global__ void __launch_bounds__(THREADS, 1) mega_kernel(
    const float* __restrict__ node_in, const float* __restrict__ b,
    const int* __restrict__ src, const int* __restrict__ dst,
    float* __restrict__ hout) {
    extern __shared__ float sm[];
    float* WihT_s = sm;                      // [64][192]
    float* WhhT_s = WihT_s + 64 * 192;       // [64][192]
    float* WTs    = WhhT_s + 64 * 192;       // [64][64]
    float* AH     = WTs + 64 * 64;           // [128][AH_STRIDE]
    float* sbrz   = AH + 128 * AH_STRIDE;    // [128]
    float* sbni   = sbrz + 128;              // [64]
    float* sbnh   = sbni + 64;               // [64]
    float* sbb    = sbnh + 64;               // [64]

    int t    = threadIdx.x;
    int cta  = blockIdx.x;
    int gtid = cta * THREADS + t;
    int lane = t & 31;
    int ds   = t & 15;
    int rs   = t >> 4;
    int db   = ds << 2;

    // ---- prologue: weights/biases into smem ONCE for the whole run ----
    for (int i = t; i < 3072; i += THREADS)
        ((float4*)WihT_s)[i] = ((const float4*)g_wihT)[i];
    for (int i = t; i < 3072; i += THREADS)
        ((float4*)WhhT_s)[i] = ((const float4*)g_whhT)[i];
    for (int i = t; i < 1024; i += THREADS)
        ((float4*)WTs)[i] = ((const float4*)g_wT)[i];
    if (t < 128) sbrz[t] = g_brz[t];
    else if (t < 192) sbni[t - 128] = g_bni[t - 128];
    else if (t < 256) sbnh[t - 192] = g_bnh[t - 192];
    else if (t < 320) sbb[t - 256] = b[t - 256];

    // ---- CSR phase A: count in-degrees ----
    for (int e = gtid; e < N_EDGES; e += GRID * THREADS)
        atomicAdd(&g_cnt[dst[e]], 1);
    grid_sync();

    // ---- CSR phase B: per-CTA-range sums ----
    {
        int i = cta * RANGE + t;
        int v = (t < RANGE && i < N_NODES) ? g_cnt[i] : 0;
        int incl = block_incl_scan(v);
        if (t == THREADS - 1) g_chunksum[cta] = incl;
    }
    grid_sync();

    // ---- CSR phase C: scan the 148 range sums (CTA 0) ----
    if (cta == 0) {
        int v = (t < GRID) ? g_chunksum[t] : 0;
        int incl = block_incl_scan(v);
        if (t < GRID) g_chunkoff[t] = incl - v;
    }
    grid_sync();

    // ---- CSR phase D: rowptr + cursor ----
    {
        int i = cta * RANGE + t;
        int v = (t < RANGE && i < N_NODES) ? g_cnt[i] : 0;
        int incl = block_incl_scan(v) + g_chunkoff[cta];
        if (t < RANGE && i < N_NODES) {
            g_rowptr[i + 1] = incl;
            g_cursor[i]     = incl - v;
        }
        if (gtid == 0) g_rowptr[0] = 0;
    }
    grid_sync();

    // ---- CSR phase E: fill (no barrier after; gemm1 below is independent,
    //      the barrier after gemm1 orders both before agg) ----
    for (int e = gtid; e < N_EDGES; e += GRID * THREADS) {
        int dd = dst[e];
        int pos = atomicAdd(&g_cursor[dd], 1);
        g_srcsorted[pos] = src[e];
    }

    // ---- gemm1 phase: wh = node_in @ W^T + b ----
    __syncthreads();
    for (int tile = cta; tile < N_TILES; tile += GRID) {
        int row0 = tile * 128;
        for (int i = t; i < 2048; i += THREADS) {
            int r = i >> 4, c4 = i & 15, g = row0 + r;
            float4 v = (g < N_NODES) ? *(const float4*)&node_in[(size_t)g * 64 + c4 * 4]
                                     : make_float4(0.f, 0.f, 0.f, 0.f);
            float* base = &AH[r * AH_STRIDE + c4 * 8];
            base[0] = v.x; base[2] = v.y; base[4] = v.z; base[6] = v.w;
        }
        __syncthreads();
        ull acc[4][2];
        {
            ull b0 = pack2f(sbb[db], sbb[db + 1]);
            ull b1 = pack2f(sbb[db + 2], sbb[db + 3]);
#pragma unroll
            for (int i = 0; i < 4; i++) { acc[i][0] = b0; acc[i][1] = b1; }
        }
#pragma unroll 8
        for (int k = 0; k < 64; k++) {
            const ull* wr = (const ull*)&WTs[k * 64 + db];
            ull w0 = wr[0], w1 = wr[1];
#pragma unroll
            for (int i = 0; i < 4; i++) {
                float x = AH[(rs + 32 * i) * AH_STRIDE + 2 * k];
                ull x2 = pack2f(x, x);
                acc[i][0] = ffma2(x2, w0, acc[i][0]);
                acc[i][1] = ffma2(x2, w1, acc[i][1]);
            }
        }
#pragma unroll
        for (int i = 0; i < 4; i++) {
            int g = row0 + rs + 32 * i;
            if (g < N_NODES) {
                float2 a = unpack2(acc[i][0]);
                float2 c = unpack2(acc[i][1]);
                *(float4*)&g_wh[(size_t)g * 64 + db] = make_float4(a.x, a.y, c.x, c.y);
            }
        }
        __syncthreads();
    }
    grid_sync();

    // ---- 3 propagation steps ----
    const float* hcur = node_in;
    for (int step = 0; step < 3; step++) {
        // agg phase: one warp per node, unroll-8 for MLP (LTS-bound)
        for (int n = gtid >> 5; n < N_NODES; n += (GRID * THREADS) >> 5) {
            int p = g_rowptr[n];
            int e = g_rowptr[n + 1];
            float ax = 0.f, ay = 0.f;
            for (; p + 8 <= e; p += 8) {
                float2 m[8];
#pragma unroll
                for (int j = 0; j < 8; j++) {
                    int s = g_srcsorted[p + j];
                    m[j] = *(const float2*)&g_wh[(size_t)s * 64 + lane * 2];
                }
#pragma unroll
                for (int j = 0; j < 8; j++) { ax += m[j].x; ay += m[j].y; }
            }
            for (; p < e; p++) {
                int s = g_srcsorted[p];
                float2 m0 = *(const float2*)&g_wh[(size_t)s * 64 + lane * 2];
                ax += m0.x; ay += m0.y;
            }
            *(float2*)&g_agg[(size_t)n * 64 + lane * 2] = make_float2(ax, ay);
        }
        grid_sync();

        // gru phase (+ fused wh for the next step)
        int do_wh = (step < 2);
        for (int tile = cta; tile < N_TILES; tile += GRID) {
            int row0 = tile * 128;
            for (int i = t; i < 2048; i += THREADS) {
                int r = i >> 4, c4 = i & 15, g = row0 + r;
                float4 av = (g < N_NODES) ? *(const float4*)&g_agg[(size_t)g * 64 + c4 * 4]
                                          : make_float4(0.f, 0.f, 0.f, 0.f);
                float4 hv = (g < N_NODES) ? *(const float4*)&hcur[(size_t)g * 64 + c4 * 4]
                                          : make_float4(0.f, 0.f, 0.f, 0.f);
                float* base = &AH[r * AH_STRIDE + c4 * 8];
                *(float2*)(base + 0) = make_float2(av.x, hv.x);
                *(float2*)(base + 2) = make_float2(av.y, hv.y);
                *(float2*)(base + 4) = make_float2(av.z, hv.z);
                *(float2*)(base + 6) = make_float2(av.w, hv.w);
            }
            __syncthreads();

            ull accR[4][2], accZ[4][2], accNi[4][2], accNh[4][2];
#pragma unroll
            for (int i = 0; i < 4; i++)
#pragma unroll
                for (int p = 0; p < 2; p++) {
                    accR[i][p] = 0ull; accZ[i][p] = 0ull;
                    accNi[i][p] = 0ull; accNh[i][p] = 0ull;
                }

#pragma unroll 4
            for (int k = 0; k < 64; k++) {
                const ull* wiR = (const ull*)&WihT_s[k * 192 + db];
                const ull* wiZ = (const ull*)&WihT_s[k * 192 + 64 + db];
                const ull* wiN = (const ull*)&WihT_s[k * 192 + 128 + db];
                const ull* whR = (const ull*)&WhhT_s[k * 192 + db];
                const ull* whZ = (const ull*)&WhhT_s[k * 192 + 64 + db];
                const ull* whN = (const ull*)&WhhT_s[k * 192 + 128 + db];
                ull wir0 = wiR[0], wir1 = wiR[1];
                ull wiz0 = wiZ[0], wiz1 = wiZ[1];
                ull win0 = wiN[0], win1 = wiN[1];
                ull whr0 = whR[0], whr1 = whR[1];
                ull whz0 = whZ[0], whz1 = whZ[1];
                ull whn0 = whN[0], whn1 = whN[1];
#pragma unroll
                for (int i = 0; i < 4; i++) {
                    int r = rs + 32 * i;
                    ull ahv = *(const ull*)&AH[r * AH_STRIDE + 2 * k];
                    float2 fah = unpack2(ahv);
                    ull a2 = pack2f(fah.x, fah.x);
                    ull h2 = pack2f(fah.y, fah.y);
                    accR[i][0] = ffma2(a2, wir0, accR[i][0]);
                    accR[i][1] = ffma2(a2, wir1, accR[i][1]);
                    accR[i][0] = ffma2(h2, whr0, accR[i][0]);
                    accR[i][1] = ffma2(h2, whr1, accR[i][1]);
                    accZ[i][0] = ffma2(a2, wiz0, accZ[i][0]);
                    accZ[i][1] = ffma2(a2, wiz1, accZ[i][1]);
                    accZ[i][0] = ffma2(h2, whz0, accZ[i][0]);
                    accZ[i][1] = ffma2(h2, whz1, accZ[i][1]);
                    accNi[i][0] = ffma2(a2, win0, accNi[i][0]);
                    accNi[i][1] = ffma2(a2, win1, accNi[i][1]);
                    accNh[i][0] = ffma2(h2, whn0, accNh[i][0]);
                    accNh[i][1] = ffma2(h2, whn1, accNh[i][1]);
                }
            }

            float outv[4][4];
#pragma unroll
            for (int i = 0; i < 4; i++) {
                int r = rs + 32 * i;
#pragma unroll
                for (int p = 0; p < 2; p++) {
                    float2 rr = unpack2(accR[i][p]);
                    float2 zz = unpack2(accZ[i][p]);
                    float2 ni = unpack2(accNi[i][p]);
                    float2 nh = unpack2(accNh[i][p]);
                    int d = db + 2 * p;
                    float r0 = sigmoid_fast(rr.x + sbrz[d]);
                    float r1 = sigmoid_fast(rr.y + sbrz[d + 1]);
                    float z0 = sigmoid_fast(zz.x + sbrz[64 + d]);
                    float z1 = sigmoid_fast(zz.y + sbrz[64 + d + 1]);
                    float n0 = tanh_fast(ni.x + sbni[d]     + r0 * (nh.x + sbnh[d]));
                    float n1 = tanh_fast(ni.y + sbni[d + 1] + r1 * (nh.y + sbnh[d + 1]));
                    float h0 = AH[r * AH_STRIDE + 2 * d + 1];
                    float h1 = AH[r * AH_STRIDE + 2 * (d + 1) + 1];
                    outv[i][2 * p]     = (1.0f - z0) * n0 + z0 * h0;
                    outv[i][2 * p + 1] = (1.0f - z1) * n1 + z1 * h1;
                }
            }

            __syncthreads();   // all AH reads done before 'a'-slot overwrite
#pragma unroll
            for (int i = 0; i < 4; i++) {
                int r = rs + 32 * i;
                int g = row0 + r;
                float4 o4 = make_float4(outv[i][0], outv[i][1], outv[i][2], outv[i][3]);
                if (g < N_NODES)
                    *(float4*)&hout[(size_t)g * 64 + db] = o4;
                AH[r * AH_STRIDE + 2 * db + 0] = o4.x;
                AH[r * AH_STRIDE + 2 * db + 2] = o4.y;
                AH[r * AH_STRIDE + 2 * db + 4] = o4.z;
                AH[r * AH_STRIDE + 2 * db + 6] = o4.w;
            }
            __syncthreads();

            if (do_wh) {
                ull acc[4][2];
                {
                    ull b0 = pack2f(sbb[db], sbb[db + 1]);
                    ull b1 = pack2f(sbb[db + 2], sbb[db + 3]);
#pragma unroll
                    for (int i = 0; i < 4; i++) { acc[i][0] = b0; acc[i][1] = b1; }
                }
#pragma unroll 8
                for (int k = 0; k < 64; k++) {
                    const ull* wr = (const ull*)&WTs[k * 64 + db];
                    ull w0 = wr[0], w1 = wr[1];
#pragma unroll
                    for (int i = 0; i < 4; i++) {
                        float x = AH[(rs + 32 * i) * AH_STRIDE + 2 * k];
                        ull x2 = pack2f(x, x);
                        acc[i][0] = ffma2(x2, w0, acc[i][0]);
                        acc[i][1] = ffma2(x2, w1, acc[i][1]);
                    }
                }
#pragma unroll
                for (int i = 0; i < 4; i++) {
                    int g = row0 + rs + 32 * i;
                    if (g < N_NODES) {
                        float2 a = unpack2(acc[i][0]);
                        float2 c = unpack2(acc[i][1]);
                        *(float4*)&g_wh[(size_t)g * 64 + db] = make_float4(a.x, a.y, c.x, c.y);
                    }
                }
            }
            __syncthreads();   // before next tile overwrites AH
        }
        if (step < 2) grid_sync();
        hcur = hout;
    }
}

// ------------------------- launch --------------------------------------------
extern "C" void kernel_launch(void* const* d_in, const int* in_sizes, int n_in,
                              void* d_out, int out_size) {
    const float *node_in = 0, *W = 0, *b = 0, *Wih = 0, *Whh = 0, *bih = 0, *bhh = 0;
    const int *src = 0, *dst = 0;
    int n12288 = 0, n192 = 0, n800k = 0;
    for (int i = 0; i < n_in; i++) {
        switch (in_sizes[i]) {
            case N_NODES * D: node_in = (const float*)d_in[i]; break;
            case D * D:       W = (const float*)d_in[i]; break;
            case D:           b = (const float*)d_in[i]; break;
            case 3 * D * D:
                if (n12288++ == 0) Wih = (const float*)d_in[i];
                else               Whh = (const float*)d_in[i];
                break;
            case 3 * D:
                if (n192++ == 0) bih = (const float*)d_in[i];
                else             bhh = (const float*)d_in[i];
                break;
            case N_EDGES:
                if (n800k++ == 0) src = (const int*)d_in[i];
                else              dst = (const int*)d_in[i];
                break;
            default: break;
        }
    }
    float* h = (float*)d_out;

    // (2*12288 + 4096 + 128*136 + 320) floats = 46,400 * 4 = 185,600 B
    const int MEGA_SMEM = (2 * 12288 + 64 * 64 + 128 * AH_STRIDE + 320) * 4;
    cudaFuncSetAttribute(mega_kernel, cudaFuncAttributeMaxDynamicSharedMemorySize, MEGA_SMEM);

    prep_kernel<<<(N_NODES + 255) / 256, 256>>>(W, Wih, Whh, bih, bhh);
    mega_kernel<<<GRID, THREADS, MEGA_SMEM>>>(node_in, b, src, dst, h);
}

// round 11
// speedup vs baseline: 1.1887x; 1.1887x over previous
#include <cuda_runtime.h>
#include <math.h>

#define N_NODES 50000
#define N_EDGES 800000
#define D 64
#define AH_STRIDE 136        // interleaved a/h rows: 2*64 + 8 pad
#define N_TILES 391          // ceil(N_NODES / 128)
#define GRU_GRID 131         // persistent: 131*3 >= 391
#define SCAN_GRID 148        // co-resident for grid barrier
#define RANGE 338            // ceil(N_NODES / SCAN_GRID)

typedef unsigned long long ull;

// ------------------------- device scratch (no allocs allowed) ---------------
// Referenced ONLY from device code (host-side use of a __device__ symbol
// passes the host shadow address, which ATS dereferences silently - R1/2 bug).
__device__ float g_agg[N_NODES * D];       // raw aggregated h (linearity trick)
__device__ int   g_rowptr[N_NODES + 1];
__device__ int   g_cnt[N_NODES];           // zero at module load; re-zeroed by fill
__device__ int   g_cursor[N_NODES];
__device__ int   g_srcsorted[N_EDGES];
__device__ int   g_chunksum[SCAN_GRID];
__device__ int   g_chunkoff[SCAN_GRID];
__device__ float g_wihT[64 * 192];
__device__ float g_whhT[64 * 192];
__device__ float g_wT[64 * 64];
__device__ float g_brz[128];
__device__ float g_bni[64];
__device__ float g_bnh[64];
// grid barrier (gen monotonic across replays; count returns to 0 - fine)
__device__ int          g_bar_count;
__device__ volatile int g_bar_gen;

// ------------------------- helpers ------------------------------------------
__device__ __forceinline__ ull ffma2(ull a, ull b, ull c) {
    ull d;
    asm("fma.rn.f32x2 %0, %1, %2, %3;" : "=l"(d) : "l"(a), "l"(b), "l"(c));
    return d;
}
__device__ __forceinline__ ull pack2f(float x, float y) {
    ull r;
    asm("mov.b64 %0, {%1, %2};" : "=l"(r) : "f"(x), "f"(y));
    return r;
}
__device__ __forceinline__ float2 unpack2(ull v) {
    float2 f;
    asm("mov.b64 {%0, %1}, %2;" : "=f"(f.x), "=f"(f.y) : "l"(v));
    return f;
}
__device__ __forceinline__ float sigmoid_fast(float x) {
    return __fdividef(1.0f, 1.0f + __expf(-x));
}
__device__ __forceinline__ float tanh_fast(float x) {
    return 1.0f - __fdividef(2.0f, __expf(2.0f * x) + 1.0f);
}

// sense-reversing grid barrier (148 CTAs co-resident; validated in R10)
__device__ __forceinline__ void grid_sync() {
    __syncthreads();
    if (threadIdx.x == 0) {
        __threadfence();
        int gen = g_bar_gen;
        if (atomicAdd(&g_bar_count, 1) == SCAN_GRID - 1) {
            g_bar_count = 0;
            __threadfence();
            g_bar_gen = gen + 1;
        } else {
            while (g_bar_gen == gen) { __nanosleep(32); }
        }
        __threadfence();
    }
    __syncthreads();
}

// block-wide inclusive scan over 512 threads
__device__ __forceinline__ int block_incl_scan(int v) {
    __shared__ int ws[16];
    int lane = threadIdx.x & 31, w = threadIdx.x >> 5;
    int x = v;
#pragma unroll
    for (int off = 1; off < 32; off <<= 1) {
        int y = __shfl_up_sync(0xffffffffu, x, off);
        if (lane >= off) x += y;
    }
    if (lane == 31) ws[w] = x;
    __syncthreads();
    if (w == 0 && lane < 16) {
        int s = ws[lane];
        int xs = s;
#pragma unroll
        for (int off = 1; off < 16; off <<= 1) {
            int y = __shfl_up_sync(0xffffu, xs, off);
            if (lane >= off) xs += y;
        }
        ws[lane] = xs - s;
    }
    __syncthreads();
    int res = x + ws[w];
    __syncthreads();
    return res;
}

// ------------------------- prep: transposes + combined biases ---------------
__global__ void prep_kernel(const float* __restrict__ W,
                            const float* __restrict__ Wih,
                            const float* __restrict__ Whh,
                            const float* __restrict__ bih,
                            const float* __restrict__ bhh) {
    int i = blockIdx.x * blockDim.x + threadIdx.x;
    if (i < 12288) {
        int k = i / 192, j = i % 192;
        g_wihT[i] = Wih[j * 64 + k];
    } else if (i < 24576) {
        int e = i - 12288; int k = e / 192, j = e % 192;
        g_whhT[e] = Whh[j * 64 + k];
    } else if (i < 28672) {
        int e = i - 24576; int k = e / 64, j = e % 64;
        g_wT[e] = W[j * 64 + k];
    } else if (i < 28800) {
        int d = i - 28672;
        g_brz[d] = bih[d] + bhh[d];
    } else if (i < 28864) {
        int d = i - 28800;
        g_bni[d] = bih[128 + d];
    } else if (i < 28928) {
        int d = i - 28864;
        g_bnh[d] = bhh[128 + d];
    }
}

// ------------------------- CSR: count ----------------------------------------
__global__ void count_kernel(const int* __restrict__ dst) {
    int e = blockIdx.x * blockDim.x + threadIdx.x;
    if (e < N_EDGES) atomicAdd(&g_cnt[dst[e]], 1);
}

// ------------------------- CSR: 3-phase scan in one kernel -------------------
__global__ void __launch_bounds__(512) csr_scan_kernel() {
    int cta = blockIdx.x, t = threadIdx.x;
    // phase B: per-CTA-range sums
    {
        int i = cta * RANGE + t;
        int v = (t < RANGE && i < N_NODES) ? g_cnt[i] : 0;
        int incl = block_incl_scan(v);
        if (t == 511) g_chunksum[cta] = incl;
    }
    grid_sync();
    // phase C: scan the 148 range sums (CTA 0)
    if (cta == 0) {
        int v = (t < SCAN_GRID) ? g_chunksum[t] : 0;
        int incl = block_incl_scan(v);
        if (t < SCAN_GRID) g_chunkoff[t] = incl - v;
    }
    grid_sync();
    // phase D: rowptr + cursor
    {
        int i = cta * RANGE + t;
        int v = (t < RANGE && i < N_NODES) ? g_cnt[i] : 0;
        int incl = block_incl_scan(v) + g_chunkoff[cta];
        if (t < RANGE && i < N_NODES) {
            g_rowptr[i + 1] = incl;
            g_cursor[i]     = incl - v;
        }
        if (cta == 0 && t == 0) g_rowptr[0] = 0;
    }
}

// ------------------------- CSR: fill (+ re-zero counts for next replay) -----
__global__ void fill_kernel(const int* __restrict__ src, const int* __restrict__ dst) {
    int e = blockIdx.x * blockDim.x + threadIdx.x;
    if (e < N_EDGES) {
        int dd = dst[e];
        int pos = atomicAdd(&g_cursor[dd], 1);
        g_srcsorted[pos] = src[e];
    }
    if (e < N_NODES) g_cnt[e] = 0;   // counts are dead after csr_scan
}

// ------------------------- aggregation of RAW h: one warp per node ----------
// Linearity: a = W*(sum h_src) + deg*b, so we aggregate h directly.
__global__ void __launch_bounds__(256) agg_kernel(const float* __restrict__ hsrc) {
    int gw = (blockIdx.x * blockDim.x + threadIdx.x) >> 5;
    if (gw >= N_NODES) return;
    int lane = threadIdx.x & 31;
    int p = g_rowptr[gw];
    int e = g_rowptr[gw + 1];
    float ax = 0.0f, ay = 0.0f;
    for (; p + 8 <= e; p += 8) {
        float2 m[8];
#pragma unroll
        for (int j = 0; j < 8; j++) {
            int s = g_srcsorted[p + j];
            m[j] = *(const float2*)&hsrc[(size_t)s * 64 + lane * 2];
        }
#pragma unroll
        for (int j = 0; j < 8; j++) { ax += m[j].x; ay += m[j].y; }
    }
    for (; p < e; p++) {
        int s = g_srcsorted[p];
        float2 m0 = *(const float2*)&hsrc[(size_t)s * 64 + lane * 2];
        ax += m0.x; ay += m0.y;
    }
    *(float2*)&g_agg[(size_t)gw * 64 + lane * 2] = make_float2(ax, ay);
}

// ------------------------- persistent GRU (A-GEMM + cell) --------------------
// 512 threads, 131 CTAs x ~3 tiles. Layout: warp = 32 dim-slots (2 dims each,
// f32x2 over dims) x 1 warp-uniform row-slot; 8 rows/thread -> weight LDS
// amortized over 8 rows (mainloop fma-bound, not crossbar-bound).
__global__ void __launch_bounds__(512) gru_kernel(
    const float* __restrict__ hin, float* __restrict__ hout,
    const float* __restrict__ b) {
    extern __shared__ float sm[];
    float* WihT_s = sm;                      // [64][192]
    float* WhhT_s = WihT_s + 64 * 192;       // [64][192]
    float* WTs    = WhhT_s + 64 * 192;       // [64][64]
    float* AH     = WTs + 64 * 64;           // [128][AH_STRIDE] interleaved a,h
    float* sdeg   = AH + 128 * AH_STRIDE;    // [128]
    float* sbrz   = sdeg + 128;              // [128]
    float* sbni   = sbrz + 128;              // [64]
    float* sbnh   = sbni + 64;               // [64]
    float* sbb    = sbnh + 64;               // [64]

    int t  = threadIdx.x;
    int ds = t & 31;        // dim slot: dims 2ds, 2ds+1
    int rs = t >> 5;        // row slot (warp-uniform): rows rs + 16*i
    int d0 = 2 * ds;

    // ---- once per CTA: weights + biases ----
    for (int i = t; i < 3072; i += 512)
        ((float4*)WihT_s)[i] = ((const float4*)g_wihT)[i];
    for (int i = t; i < 3072; i += 512)
        ((float4*)WhhT_s)[i] = ((const float4*)g_whhT)[i];
    for (int i = t; i < 1024; i += 512)
        ((float4*)WTs)[i] = ((const float4*)g_wT)[i];
    if (t < 128) sbrz[t] = g_brz[t];
    else if (t < 192) sbni[t - 128] = g_bni[t - 128];
    else if (t < 256) sbnh[t - 192] = g_bnh[t - 192];
    else if (t < 320) sbb[t - 256] = b[t - 256];

    for (int tile = blockIdx.x; tile < N_TILES; tile += gridDim.x) {
        int row0 = tile * 128;

        // ---- stage: AH interleaved (hagg, h) + degree ----
        for (int i = t; i < 2048; i += 512) {
            int r = i >> 4, c4 = i & 15, g = row0 + r;
            float4 av = (g < N_NODES) ? *(const float4*)&g_agg[(size_t)g * 64 + c4 * 4]
                                      : make_float4(0.f, 0.f, 0.f, 0.f);
            float4 hv = (g < N_NODES) ? *(const float4*)&hin[(size_t)g * 64 + c4 * 4]
                                      : make_float4(0.f, 0.f, 0.f, 0.f);
            float* base = &AH[r * AH_STRIDE + c4 * 8];
            *(float2*)(base + 0) = make_float2(av.x, hv.x);
            *(float2*)(base + 2) = make_float2(av.y, hv.y);
            *(float2*)(base + 4) = make_float2(av.z, hv.z);
            *(float2*)(base + 6) = make_float2(av.w, hv.w);
        }
        if (t < 128) {
            int g = row0 + t;
            sdeg[t] = (g < N_NODES) ? (float)(g_rowptr[g + 1] - g_rowptr[g]) : 0.0f;
        }
        __syncthreads();

        // ---- A-GEMM: A = W * hagg + deg * b  ('a' slots hold hagg) ----
        ull accA[8];
        {
            float bb0 = sbb[d0], bb1 = sbb[d0 + 1];
#pragma unroll
            for (int i = 0; i < 8; i++) {
                float dg = sdeg[rs + 16 * i];
                accA[i] = pack2f(dg * bb0, dg * bb1);
            }
        }
#pragma unroll 4
        for (int kk = 0; kk < 32; kk++) {      // 2 k per iter via float4 broadcast
            int k = 2 * kk;
            ull w0 = *(const ull*)&WTs[k * 64 + d0];
            ull w1 = *(const ull*)&WTs[(k + 1) * 64 + d0];
#pragma unroll
            for (int i = 0; i < 8; i++) {
                int r = rs + 16 * i;
                float4 q = *(const float4*)&AH[r * AH_STRIDE + 2 * k]; // (a_k,h_k,a_k1,h_k1)
                accA[i] = ffma2(pack2f(q.x, q.x), w0, accA[i]);
                accA[i] = ffma2(pack2f(q.z, q.z), w1, accA[i]);
            }
        }
        __syncthreads();   // all hagg reads done
#pragma unroll
        for (int i = 0; i < 8; i++) {
            int r = rs + 16 * i;
            float2 av = unpack2(accA[i]);
            AH[r * AH_STRIDE + 4 * ds + 0] = av.x;   // dim d0   -> slot 2*d0
            AH[r * AH_STRIDE + 4 * ds + 2] = av.y;   // dim d0+1 -> slot 2*(d0+1)
        }
        __syncthreads();

        // ---- GRU mainloop ----
        ull accR[8], accZ[8], accNi[8], accNh[8];
#pragma unroll
        for (int i = 0; i < 8; i++) {
            accR[i] = 0ull; accZ[i] = 0ull; accNi[i] = 0ull; accNh[i] = 0ull;
        }
#pragma unroll 4
        for (int k = 0; k < 64; k++) {
            ull wir = *(const ull*)&WihT_s[k * 192 + d0];
            ull wiz = *(const ull*)&WihT_s[k * 192 + 64 + d0];
            ull win = *(const ull*)&WihT_s[k * 192 + 128 + d0];
            ull whr = *(const ull*)&WhhT_s[k * 192 + d0];
            ull whz = *(const ull*)&WhhT_s[k * 192 + 64 + d0];
            ull whn = *(const ull*)&WhhT_s[k * 192 + 128 + d0];
#pragma unroll
            for (int i = 0; i < 8; i++) {
                int r = rs + 16 * i;
                float2 fah = unpack2(*(const ull*)&AH[r * AH_STRIDE + 2 * k]);
                ull a2 = pack2f(fah.x, fah.x);
                ull h2 = pack2f(fah.y, fah.y);
                accR[i]  = ffma2(a2, wir, accR[i]);
                accR[i]  = ffma2(h2, whr, accR[i]);
                accZ[i]  = ffma2(a2, wiz, accZ[i]);
                accZ[i]  = ffma2(h2, whz, accZ[i]);
                accNi[i] = ffma2(a2, win, accNi[i]);
                accNh[i] = ffma2(h2, whn, accNh[i]);
            }
        }

        // ---- gates + output ----
#pragma unroll
        for (int i = 0; i < 8; i++) {
            int r = rs + 16 * i;
            int g = row0 + r;
            float2 rr = unpack2(accR[i]);
            float2 zz = unpack2(accZ[i]);
            float2 ni = unpack2(accNi[i]);
            float2 nh = unpack2(accNh[i]);
            float r0 = sigmoid_fast(rr.x + sbrz[d0]);
            float r1 = sigmoid_fast(rr.y + sbrz[d0 + 1]);
            float z0 = sigmoid_fast(zz.x + sbrz[64 + d0]);
            float z1 = sigmoid_fast(zz.y + sbrz[64 + d0 + 1]);
            float n0 = tanh_fast(ni.x + sbni[d0]     + r0 * (nh.x + sbnh[d0]));
            float n1 = tanh_fast(ni.y + sbni[d0 + 1] + r1 * (nh.y + sbnh[d0 + 1]));
            float h0 = AH[r * AH_STRIDE + 4 * ds + 1];       // h slot of dim d0
            float h1 = AH[r * AH_STRIDE + 4 * ds + 3];       // h slot of dim d0+1
            float o0 = (1.0f - z0) * n0 + z0 * h0;
            float o1 = (1.0f - z1) * n1 + z1 * h1;
            if (g < N_NODES)
                *(float2*)&hout[(size_t)g * 64 + d0] = make_float2(o0, o1);
        }
        __syncthreads();   // before next tile overwrites AH
    }
}

// ------------------------- launch --------------------------------------------
extern "C" void kernel_launch(void* const* d_in, const int* in_sizes, int n_in,
                              void* d_out, int out_size) {
    const float *node_in = 0, *W = 0, *b = 0, *Wih = 0, *Whh = 0, *bih = 0, *bhh = 0;
    const int *src = 0, *dst = 0;
    int n12288 = 0, n192 = 0, n800k = 0;
    for (int i = 0; i < n_in; i++) {
        switch (in_sizes[i]) {
            case N_NODES * D: node_in = (const float*)d_in[i]; break;
            case D * D:       W = (const float*)d_in[i]; break;
            case D:           b = (const float*)d_in[i]; break;
            case 3 * D * D:
                if (n12288++ == 0) Wih = (const float*)d_in[i];
                else               Whh = (const float*)d_in[i];
                break;
            case 3 * D:
                if (n192++ == 0) bih = (const float*)d_in[i];
                else             bhh = (const float*)d_in[i];
                break;
            case N_EDGES:
                if (n800k++ == 0) src = (const int*)d_in[i];
                else              dst = (const int*)d_in[i];
                break;
            default: break;
        }
    }
    float* h = (float*)d_out;

    // (2*12288 + 4096 + 128*136 + 128 + 320) floats = 46,528 * 4 = 186,112 B
    const int GRU_SMEM = (2 * 12288 + 64 * 64 + 128 * AH_STRIDE + 128 + 320) * 4;
    cudaFuncSetAttribute(gru_kernel, cudaFuncAttributeMaxDynamicSharedMemorySize, GRU_SMEM);

    const int agg_grid = (N_NODES * 32 + 255) / 256;

    prep_kernel<<<(28928 + 255) / 256, 256>>>(W, Wih, Whh, bih, bhh);  // 0
    count_kernel<<<(N_EDGES + 255) / 256, 256>>>(dst);                 // 1
    csr_scan_kernel<<<SCAN_GRID, 512>>>();                             // 2
    fill_kernel<<<(N_EDGES + 255) / 256, 256>>>(src, dst);             // 3

    // step 0
    agg_kernel<<<agg_grid, 256>>>(node_in);                            // 4
    gru_kernel<<<GRU_GRID, 512, GRU_SMEM>>>(node_in, h, b);            // 5 (ncu -s 5)
    // step 1
    agg_kernel<<<agg_grid, 256>>>(h);                                  // 6
    gru_kernel<<<GRU_GRID, 512, GRU_SMEM>>>(h, h, b);                  // 7
    // step 2
    agg_kernel<<<agg_grid, 256>>>(h);                                  // 8
    gru_kernel<<<GRU_GRID, 512, GRU_SMEM>>>(h, h, b);                  // 9
}

// round 13
// speedup vs baseline: 2.1322x; 1.7938x over previous
#include <cuda_runtime.h>
#include <cuda_bf16.h>
#include <math.h>
#include <stdint.h>

#define N_NODES 50000
#define N_EDGES 800000
#define D 64
#define SCAN_GRID 148
#define RANGE 338
#define N_TILES 391          // ceil(N_NODES/128)
#define GRU_GRID 131
#define THREADS 256

// ---- smem layout (u32 units for frags; byte offsets) -------------------------
// Wih frags: 24 ntiles x 4 ktiles x 32 lanes x 2 u32 = 6144 u32 per split
// Whh same; W: 8 ntiles -> 2048 u32 per split
#define U_WIH_HI 0
#define U_WIH_LO 6144
#define U_WHH_HI 12288
#define U_WHH_LO 18432
#define U_WW_HI  24576
#define U_WW_LO  26624
#define U_TOTAL  28672                       // 114,688 B
#define OFF_BRZ  (U_TOTAL * 4)               // f32[128]
#define OFF_BNI  (OFF_BRZ + 512)             // f32[64]
#define OFF_BNH  (OFF_BNI + 256)             // f32[64]
#define OFF_BB   (OFF_BNH + 256)             // f32[64]
#define SMEM_BYTES (OFF_BB + 256)

// ---- device scratch (device-code-only references; R1/2 ATS lesson) -----------
__device__ float    g_agg[N_NODES * D];
__device__ int      g_rowptr[N_NODES + 1];
__device__ int      g_cnt[N_NODES];
__device__ int      g_cursor[N_NODES];
__device__ int      g_srcsorted[N_EDGES];
__device__ int      g_chunksum[SCAN_GRID];
__device__ int      g_chunkoff[SCAN_GRID];
__device__ uint32_t g_wihF[2][6144];         // [hi/lo][frag u32]
__device__ uint32_t g_whhF[2][6144];
__device__ uint32_t g_wF[2][2048];
__device__ float    g_brz[128];
__device__ float    g_bni[64];
__device__ float    g_bnh[64];
__device__ int          g_bar_count;
__device__ volatile int g_bar_gen;

// ---- helpers ------------------------------------------------------------------
__device__ __forceinline__ float sigmoid_fast(float x) {
    return __fdividef(1.0f, 1.0f + __expf(-x));
}
__device__ __forceinline__ float tanh_fast(float x) {
    return 1.0f - __fdividef(2.0f, __expf(2.0f * x) + 1.0f);
}
__device__ __forceinline__ uint32_t pack_bf2(__nv_bfloat16 a, __nv_bfloat16 b) {
    __nv_bfloat162 p = __halves2bfloat162(a, b);   // a -> low 16 bits
    return *reinterpret_cast<uint32_t*>(&p);
}
// split pair (v.x, v.y) into hi/lo packed bf16x2
__device__ __forceinline__ void split2(float2 v, uint32_t& h, uint32_t& l) {
    __nv_bfloat16 h0 = __float2bfloat16(v.x);
    __nv_bfloat16 l0 = __float2bfloat16(v.x - __bfloat162float(h0));
    __nv_bfloat16 h1 = __float2bfloat16(v.y);
    __nv_bfloat16 l1 = __float2bfloat16(v.y - __bfloat162float(h1));
    h = pack_bf2(h0, h1);
    l = pack_bf2(l0, l1);
}
__device__ __forceinline__ float2 unsplit2(uint32_t h, uint32_t l) {
    __nv_bfloat162 hb = *reinterpret_cast<__nv_bfloat162*>(&h);
    __nv_bfloat162 lb = *reinterpret_cast<__nv_bfloat162*>(&l);
    return make_float2(__bfloat162float(hb.x) + __bfloat162float(lb.x),
                       __bfloat162float(hb.y) + __bfloat162float(lb.y));
}

// warp-level bf16 MMA: D[16,8] += A[16,16] * B[16,8]
__device__ __forceinline__ void mma16816(float* c, const uint32_t* a,
                                         uint32_t b0, uint32_t b1) {
    asm volatile(
        "mma.sync.aligned.m16n8k16.row.col.f32.bf16.bf16.f32 "
        "{%0,%1,%2,%3}, {%4,%5,%6,%7}, {%8,%9}, {%0,%1,%2,%3};"
        : "+f"(c[0]), "+f"(c[1]), "+f"(c[2]), "+f"(c[3])
        : "r"(a[0]), "r"(a[1]), "r"(a[2]), "r"(a[3]), "r"(b0), "r"(b1));
}

// accumulate 8-ntile block: C += X * W^T (3-product split)
__device__ __forceinline__ void gemm_block(
    float C[8][4], const uint32_t* Ahi, const uint32_t* Alo,
    const uint32_t* whi, const uint32_t* wlo, int ntBase, int lane) {
#pragma unroll
    for (int kt = 0; kt < 4; kt++) {
        const uint32_t* ah = Ahi + 4 * kt;
        const uint32_t* al = Alo + 4 * kt;
#pragma unroll
        for (int nt = 0; nt < 8; nt++) {
            int idx = (((ntBase + nt) * 4 + kt) * 32 + lane) * 2;
            uint32_t bh0 = whi[idx], bh1 = whi[idx + 1];
            uint32_t bl0 = wlo[idx], bl1 = wlo[idx + 1];
            mma16816(C[nt], ah, bh0, bh1);   // hi*hi
            mma16816(C[nt], ah, bl0, bl1);   // hi*lo
            mma16816(C[nt], al, bh0, bh1);   // lo*hi
        }
    }
}

// load 16-row x 64-col X slice as split A-fragments (rows r0,r1 = g,g+8)
__device__ __forceinline__ void load_x_frags(
    const float* __restrict__ X, int r0, int r1, int tig,
    uint32_t* hi, uint32_t* lo) {
    bool v0 = (r0 < N_NODES), v1 = (r1 < N_NODES);
    const float2 z2 = make_float2(0.f, 0.f);
#pragma unroll
    for (int kt = 0; kt < 4; kt++) {
        int cb = 16 * kt + 2 * tig;
        float2 p0 = v0 ? *(const float2*)&X[(size_t)r0 * 64 + cb]     : z2;
        float2 p1 = v1 ? *(const float2*)&X[(size_t)r1 * 64 + cb]     : z2;
        float2 p2 = v0 ? *(const float2*)&X[(size_t)r0 * 64 + cb + 8] : z2;
        float2 p3 = v1 ? *(const float2*)&X[(size_t)r1 * 64 + cb + 8] : z2;
        split2(p0, hi[4 * kt + 0], lo[4 * kt + 0]);
        split2(p1, hi[4 * kt + 1], lo[4 * kt + 1]);
        split2(p2, hi[4 * kt + 2], lo[4 * kt + 2]);
        split2(p3, hi[4 * kt + 3], lo[4 * kt + 3]);
    }
}

// grid barrier (148 co-resident CTAs; validated R10)
__device__ __forceinline__ void grid_sync() {
    __syncthreads();
    if (threadIdx.x == 0) {
        __threadfence();
        int gen = g_bar_gen;
        if (atomicAdd(&g_bar_count, 1) == SCAN_GRID - 1) {
            g_bar_count = 0;
            __threadfence();
            g_bar_gen = gen + 1;
        } else {
            while (g_bar_gen == gen) { __nanosleep(32); }
        }
        __threadfence();
    }
    __syncthreads();
}

__device__ __forceinline__ int block_incl_scan(int v) {
    __shared__ int ws[16];
    int lane = threadIdx.x & 31, w = threadIdx.x >> 5;
    int x = v;
#pragma unroll
    for (int off = 1; off < 32; off <<= 1) {
        int y = __shfl_up_sync(0xffffffffu, x, off);
        if (lane >= off) x += y;
    }
    if (lane == 31) ws[w] = x;
    __syncthreads();
    if (w == 0 && lane < 16) {
        int s = ws[lane];
        int xs = s;
#pragma unroll
        for (int off = 1; off < 16; off <<= 1) {
            int y = __shfl_up_sync(0xffffu, xs, off);
            if (lane >= off) xs += y;
        }
        ws[lane] = xs - s;
    }
    __syncthreads();
    int res = x + ws[w];
    __syncthreads();
    return res;
}

// ------------------------- prep: weights -> B-fragment layout ----------------
// B-frag (m16n8k16): reg0 = B[k=2tig,2tig+1][n=g]; reg1 = k+8. W stored [n][k]
// row-major, so both regs are consecutive-k pairs from row n.
__device__ __forceinline__ void put_wfrag(uint32_t* hiArr, uint32_t* loArr,
                                          const float* Wmat, int n, int k0) {
    int nt = n >> 3, g = n & 7;
    int kt = k0 >> 4, rem = k0 & 15;
    int breg = (rem >= 8) ? 1 : 0;
    int tig = (rem >> 1) & 3;
    int idx = ((nt * 4 + kt) * 32 + (g * 4 + tig)) * 2 + breg;
    uint32_t h, l;
    split2(make_float2(Wmat[n * 64 + k0], Wmat[n * 64 + k0 + 1]), h, l);
    hiArr[idx] = h;
    loArr[idx] = l;
}

__global__ void prep_kernel(const float* __restrict__ W,
                            const float* __restrict__ Wih,
                            const float* __restrict__ Whh,
                            const float* __restrict__ bih,
                            const float* __restrict__ bhh) {
    int i = blockIdx.x * blockDim.x + threadIdx.x;
    if (i < 6144) {                       // Wih pairs: n = i>>5, k0 = 2*(i&31)
        put_wfrag(g_wihF[0], g_wihF[1], Wih, i >> 5, 2 * (i & 31));
    } else if (i < 12288) {
        int e = i - 6144;
        put_wfrag(g_whhF[0], g_whhF[1], Whh, e >> 5, 2 * (e & 31));
    } else if (i < 14336) {
        int e = i - 12288;
        put_wfrag(g_wF[0], g_wF[1], W, e >> 5, 2 * (e & 31));
    } else if (i < 14464) {
        int d = i - 14336;
        g_brz[d] = bih[d] + bhh[d];
    } else if (i < 14528) {
        int d = i - 14464;
        g_bni[d] = bih[128 + d];
    } else if (i < 14592) {
        int d = i - 14528;
        g_bnh[d] = bhh[128 + d];
    }
    if (i < N_NODES) g_cnt[i] = 0;
}

// ------------------------- CSR build ------------------------------------------
__global__ void count_kernel(const int* __restrict__ dst) {
    int e = blockIdx.x * blockDim.x + threadIdx.x;
    if (e < N_EDGES) atomicAdd(&g_cnt[dst[e]], 1);
}

__global__ void __launch_bounds__(512) csr_scan_kernel() {
    int cta = blockIdx.x, t = threadIdx.x;
    {
        int i = cta * RANGE + t;
        int v = (t < RANGE && i < N_NODES) ? g_cnt[i] : 0;
        int incl = block_incl_scan(v);
        if (t == 511) g_chunksum[cta] = incl;
    }
    grid_sync();
    if (cta == 0) {
        int v = (t < SCAN_GRID) ? g_chunksum[t] : 0;
        int incl = block_incl_scan(v);
        if (t < SCAN_GRID) g_chunkoff[t] = incl - v;
    }
    grid_sync();
    {
        int i = cta * RANGE + t;
        int v = (t < RANGE && i < N_NODES) ? g_cnt[i] : 0;
        int incl = block_incl_scan(v) + g_chunkoff[cta];
        if (t < RANGE && i < N_NODES) {
            g_rowptr[i + 1] = incl;
            g_cursor[i]     = incl - v;
        }
        if (cta == 0 && t == 0) g_rowptr[0] = 0;
    }
}

__global__ void fill_kernel(const int* __restrict__ src, const int* __restrict__ dst) {
    int e = blockIdx.x * blockDim.x + threadIdx.x;
    if (e < N_EDGES) {
        int dd = dst[e];
        int pos = atomicAdd(&g_cursor[dd], 1);
        g_srcsorted[pos] = src[e];
    }
    if (e < N_NODES) g_cnt[e] = 0;   // reset for next replay
}

// ------------------------- aggregation of raw h: one warp per node -----------
__global__ void __launch_bounds__(256) agg_kernel(const float* __restrict__ hsrc) {
    int gw = (blockIdx.x * blockDim.x + threadIdx.x) >> 5;
    if (gw >= N_NODES) return;
    int lane = threadIdx.x & 31;
    int p = g_rowptr[gw];
    int e = g_rowptr[gw + 1];
    float ax = 0.0f, ay = 0.0f;
    for (; p + 8 <= e; p += 8) {
        float2 m[8];
#pragma unroll
        for (int j = 0; j < 8; j++) {
            int s = g_srcsorted[p + j];
            m[j] = *(const float2*)&hsrc[(size_t)s * 64 + lane * 2];
        }
#pragma unroll
        for (int j = 0; j < 8; j++) { ax += m[j].x; ay += m[j].y; }
    }
    for (; p < e; p++) {
        int s = g_srcsorted[p];
        float2 m0 = *(const float2*)&hsrc[(size_t)s * 64 + lane * 2];
        ax += m0.x; ay += m0.y;
    }
    *(float2*)&g_agg[(size_t)gw * 64 + lane * 2] = make_float2(ax, ay);
}

// ------------------------- HMMA GRU --------------------------------------------
// Persistent 131 CTAs x ~3 tiles; 8 warps x 16 rows each; no intra-loop syncs.
// Per warp-tile: load hagg/h as split A-frags; A-GEMM (W) in tensor cores;
// C_A + deg*b converts in-register to A-frags; gates R/HN/IN/Z via HMMA blocks.
__global__ void __launch_bounds__(THREADS) gru_kernel(
    const float* __restrict__ hin, float* __restrict__ hout,
    const float* __restrict__ b) {
    extern __shared__ uint32_t smu[];
    float* sbrz = (float*)((char*)smu + OFF_BRZ);
    float* sbni = (float*)((char*)smu + OFF_BNI);
    float* sbnh = (float*)((char*)smu + OFF_BNH);
    float* sbb  = (float*)((char*)smu + OFF_BB);

    int t = threadIdx.x;
    int lane = t & 31;
    int w = t >> 5;
    int g = lane >> 2;
    int tig = lane & 3;

    // ---- prologue: copy weight fragments + biases (once per CTA) ----
    {
        uint4* d = (uint4*)smu;
        const uint4* s;
        s = (const uint4*)g_wihF[0];
        for (int i = t; i < 1536; i += THREADS) d[i] = s[i];
        s = (const uint4*)g_wihF[1];
        for (int i = t; i < 1536; i += THREADS) d[U_WIH_LO / 4 + i] = s[i];
        s = (const uint4*)g_whhF[0];
        for (int i = t; i < 1536; i += THREADS) d[U_WHH_HI / 4 + i] = s[i];
        s = (const uint4*)g_whhF[1];
        for (int i = t; i < 1536; i += THREADS) d[U_WHH_LO / 4 + i] = s[i];
        s = (const uint4*)g_wF[0];
        for (int i = t; i < 512; i += THREADS) d[U_WW_HI / 4 + i] = s[i];
        s = (const uint4*)g_wF[1];
        for (int i = t; i < 512; i += THREADS) d[U_WW_LO / 4 + i] = s[i];
    }
    if (t < 128) sbrz[t] = g_brz[t];
    else if (t < 192) sbni[t - 128] = g_bni[t - 128];
    else if (t < 256) sbnh[t - 192] = g_bnh[t - 192];
    if (t < 64) sbb[t] = b[t];
    __syncthreads();

    const uint32_t* WIHh = smu + U_WIH_HI;
    const uint32_t* WIHl = smu + U_WIH_LO;
    const uint32_t* WHHh = smu + U_WHH_HI;
    const uint32_t* WHHl = smu + U_WHH_LO;
    const uint32_t* WWh  = smu + U_WW_HI;
    const uint32_t* WWl  = smu + U_WW_LO;

    for (int tile = blockIdx.x; tile < N_TILES; tile += gridDim.x) {
        int R0 = tile * 128 + w * 16;
        int r0 = R0 + g;
        int r1 = R0 + g + 8;

        // ---- operand fragments ----
        uint32_t Ahi[16], Alo[16];   // hagg -> later A (post-GEMM)
        uint32_t Hhi[16], Hlo[16];   // h
        load_x_frags(g_agg, r0, r1, tig, Ahi, Alo);
        load_x_frags(hin,   r0, r1, tig, Hhi, Hlo);

        float deg0 = (r0 < N_NODES) ? (float)(g_rowptr[r0 + 1] - g_rowptr[r0]) : 0.f;
        float deg1 = (r1 < N_NODES) ? (float)(g_rowptr[r1 + 1] - g_rowptr[r1]) : 0.f;

        // ---- A-GEMM: C_A = hagg @ W^T + deg*b ----
        float CA[8][4];
#pragma unroll
        for (int nt = 0; nt < 8; nt++)
#pragma unroll
            for (int j = 0; j < 4; j++) CA[nt][j] = 0.f;
        gemm_block(CA, Ahi, Alo, WWh, WWl, 0, lane);
#pragma unroll
        for (int nt = 0; nt < 8; nt++) {
            int c = 8 * nt + 2 * tig;
            CA[nt][0] += deg0 * sbb[c];
            CA[nt][1] += deg0 * sbb[c + 1];
            CA[nt][2] += deg1 * sbb[c];
            CA[nt][3] += deg1 * sbb[c + 1];
        }
        // convert C_A -> A fragments (layout coincidence: C(m16n8) == A(m16k16) slices)
#pragma unroll
        for (int kt = 0; kt < 4; kt++) {
            split2(make_float2(CA[2 * kt][0],     CA[2 * kt][1]),
                   Ahi[4 * kt + 0], Alo[4 * kt + 0]);
            split2(make_float2(CA[2 * kt][2],     CA[2 * kt][3]),
                   Ahi[4 * kt + 1], Alo[4 * kt + 1]);
            split2(make_float2(CA[2 * kt + 1][0], CA[2 * kt + 1][1]),
                   Ahi[4 * kt + 2], Alo[4 * kt + 2]);
            split2(make_float2(CA[2 * kt + 1][2], CA[2 * kt + 1][3]),
                   Ahi[4 * kt + 3], Alo[4 * kt + 3]);
        }

        // ---- R gate ----
        float P[8][4];   // r, then p = r*(hn+bnh), then n
        float CB[8][4];
#pragma unroll
        for (int nt = 0; nt < 8; nt++)
#pragma unroll
            for (int j = 0; j < 4; j++) P[nt][j] = 0.f;
        gemm_block(P, Ahi, Alo, WIHh, WIHl, 0, lane);
        gemm_block(P, Hhi, Hlo, WHHh, WHHl, 0, lane);
#pragma unroll
        for (int nt = 0; nt < 8; nt++) {
            int c = 8 * nt + 2 * tig;
            P[nt][0] = sigmoid_fast(P[nt][0] + sbrz[c]);
            P[nt][1] = sigmoid_fast(P[nt][1] + sbrz[c + 1]);
            P[nt][2] = sigmoid_fast(P[nt][2] + sbrz[c]);
            P[nt][3] = sigmoid_fast(P[nt][3] + sbrz[c + 1]);
        }

        // ---- h_n: P = r * (h@WhhN + bnh) ----
#pragma unroll
        for (int nt = 0; nt < 8; nt++)
#pragma unroll
            for (int j = 0; j < 4; j++) CB[nt][j] = 0.f;
        gemm_block(CB, Hhi, Hlo, WHHh, WHHl, 16, lane);
#pragma unroll
        for (int nt = 0; nt < 8; nt++) {
            int c = 8 * nt + 2 * tig;
            P[nt][0] *= (CB[nt][0] + sbnh[c]);
            P[nt][1] *= (CB[nt][1] + sbnh[c + 1]);
            P[nt][2] *= (CB[nt][2] + sbnh[c]);
            P[nt][3] *= (CB[nt][3] + sbnh[c + 1]);
        }

        // ---- i_n: P = n = tanh(a@WihN + bni + P) ----
#pragma unroll
        for (int nt = 0; nt < 8; nt++)
#pragma unroll
            for (int j = 0; j < 4; j++) CB[nt][j] = 0.f;
        gemm_block(CB, Ahi, Alo, WIHh, WIHl, 16, lane);
#pragma unroll
        for (int nt = 0; nt < 8; nt++) {
            int c = 8 * nt + 2 * tig;
            P[nt][0] = tanh_fast(CB[nt][0] + sbni[c]     + P[nt][0]);
            P[nt][1] = tanh_fast(CB[nt][1] + sbni[c + 1] + P[nt][1]);
            P[nt][2] = tanh_fast(CB[nt][2] + sbni[c]     + P[nt][2]);
            P[nt][3] = tanh_fast(CB[nt][3] + sbni[c + 1] + P[nt][3]);
        }

        // ---- Z gate + output ----
#pragma unroll
        for (int nt = 0; nt < 8; nt++)
#pragma unroll
            for (int j = 0; j < 4; j++) CB[nt][j] = 0.f;
        gemm_block(CB, Ahi, Alo, WIHh, WIHl, 8, lane);
        gemm_block(CB, Hhi, Hlo, WHHh, WHHl, 8, lane);
#pragma unroll
        for (int nt = 0; nt < 8; nt++) {
            int c = 8 * nt + 2 * tig;
            float z0 = sigmoid_fast(CB[nt][0] + sbrz[64 + c]);
            float z1 = sigmoid_fast(CB[nt][1] + sbrz[64 + c + 1]);
            float z2 = sigmoid_fast(CB[nt][2] + sbrz[64 + c]);
            float z3 = sigmoid_fast(CB[nt][3] + sbrz[64 + c + 1]);
            // h values from fragments (hi+lo reconstruction, err ~1e-5 rel)
            int fb = 4 * (nt >> 1) + ((nt & 1) ? 2 : 0);
            float2 hrow0 = unsplit2(Hhi[fb],     Hlo[fb]);       // row g,   cols c,c+1
            float2 hrow1 = unsplit2(Hhi[fb + 1], Hlo[fb + 1]);   // row g+8
            float o0 = (1.f - z0) * P[nt][0] + z0 * hrow0.x;
            float o1 = (1.f - z1) * P[nt][1] + z1 * hrow0.y;
            float o2 = (1.f - z2) * P[nt][2] + z2 * hrow1.x;
            float o3 = (1.f - z3) * P[nt][3] + z3 * hrow1.y;
            if (r0 < N_NODES)
                *(float2*)&hout[(size_t)r0 * 64 + c] = make_float2(o0, o1);
            if (r1 < N_NODES)
                *(float2*)&hout[(size_t)r1 * 64 + c] = make_float2(o2, o3);
        }
    }
}

// ------------------------- launch ----------------------------------------------
extern "C" void kernel_launch(void* const* d_in, const int* in_sizes, int n_in,
                              void* d_out, int out_size) {
    const float *node_in = 0, *W = 0, *b = 0, *Wih = 0, *Whh = 0, *bih = 0, *bhh = 0;
    const int *src = 0, *dst = 0;
    int n12288 = 0, n192 = 0, n800k = 0;
    for (int i = 0; i < n_in; i++) {
        switch (in_sizes[i]) {
            case N_NODES * D: node_in = (const float*)d_in[i]; break;
            case D * D:       W = (const float*)d_in[i]; break;
            case D:           b = (const float*)d_in[i]; break;
            case 3 * D * D:
                if (n12288++ == 0) Wih = (const float*)d_in[i];
                else               Whh = (const float*)d_in[i];
                break;
            case 3 * D:
                if (n192++ == 0) bih = (const float*)d_in[i];
                else             bhh = (const float*)d_in[i];
                break;
            case N_EDGES:
                if (n800k++ == 0) src = (const int*)d_in[i];
                else              dst = (const int*)d_in[i];
                break;
            default: break;
        }
    }
    float* h = (float*)d_out;

    cudaFuncSetAttribute(gru_kernel, cudaFuncAttributeMaxDynamicSharedMemorySize,
                         SMEM_BYTES);

    const int agg_grid = (N_NODES * 32 + 255) / 256;

    prep_kernel<<<(N_NODES + 255) / 256, 256>>>(W, Wih, Whh, bih, bhh);
    count_kernel<<<(N_EDGES + 255) / 256, 256>>>(dst);
    csr_scan_kernel<<<SCAN_GRID, 512>>>();
    fill_kernel<<<(N_EDGES + 255) / 256, 256>>>(src, dst);

    // step 0
    agg_kernel<<<agg_grid, 256>>>(node_in);
    gru_kernel<<<GRU_GRID, THREADS, SMEM_BYTES>>>(node_in, h, b);
    // step 1
    agg_kernel<<<agg_grid, 256>>>(h);
    gru_kernel<<<GRU_GRID, THREADS, SMEM_BYTES>>>(h, h, b);
    // step 2
    agg_kernel<<<agg_grid, 256>>>(h);
    gru_kernel<<<GRU_GRID, THREADS, SMEM_BYTES>>>(h, h, b);
}